// round 14
// baseline (speedup 1.0000x reference)
#include <cuda_runtime.h>
#include <cuda_bf16.h>
#include <math.h>
#include <stdint.h>

// ---------------------------------------------------------------------------
// GAT: 3 layers (H=4,C=64) -> (H=4,C=64) -> (H=1,C=64) -> FC 64->10
// N=50000 nodes, E=800000 edges (+N self loops)
// R14: occupancy-first GEMM. Warp tile 16x64 (MI=1) for ALL layers, BN=64,
// __launch_bounds__(256,3) -> 3 CTAs/SM (24 warps). Permuted-tf32 operands
// retained (wconv for weights, permuted activations from gat_h4).
// ---------------------------------------------------------------------------

#define MAX_N 50000
#define MAX_E 800000
#define MAX_ETOT (MAX_E + MAX_N)
#define NEG_SLOPE 0.2f
#define SCAN_BS 512

// Scratch (static __device__ globals; allocation-free)
__device__ float          g_bufB[MAX_N * 256];   // permuted tf32-rounded activations
__device__ __nv_bfloat16  g_xpb[MAX_N * 256];    // bf16 transformed features (natural)
__device__ float          g_wtf[128 * 256 + 256 * 256 + 256 * 64];  // permuted tf32 weights
__device__ float g_s[MAX_N * 4];
__device__ float g_d[MAX_N * 4];
__device__ int   g_count[MAX_N];
__device__ int   g_excl[MAX_N];
__device__ int   g_cursor[MAX_N];
__device__ int   g_ptr[MAX_N + 1];
__device__ int   g_bsum[256];
__device__ int   g_csr[MAX_ETOT];

static inline int ceil_div(int a, int b) { return (a + b - 1) / b; }

// ---------------------------------------------------------------------------
// TF32 helpers
// ---------------------------------------------------------------------------
__device__ __forceinline__ uint32_t f2tf32(float f)
{
    uint32_t o;
    asm("cvt.rna.tf32.f32 %0, %1;" : "=r"(o) : "f"(f));
    return o;
}

__device__ __forceinline__ void mma_tf32(float* c, const uint32_t* a, const uint32_t* b)
{
    asm volatile(
        "mma.sync.aligned.m16n8k8.row.col.f32.tf32.tf32.f32 "
        "{%0,%1,%2,%3}, {%4,%5,%6,%7}, {%8,%9}, {%0,%1,%2,%3};\n"
        : "+f"(c[0]), "+f"(c[1]), "+f"(c[2]), "+f"(c[3])
        : "r"(a[0]), "r"(a[1]), "r"(a[2]), "r"(a[3]), "r"(b[0]), "r"(b[1]));
}

// ---------------------------------------------------------------------------
// Weight pre-conversion: W[K][Nw] (row-major) -> out[n*K + t*32 + k'] with
// k' = 8*(k_local%4) + k_local/4, value = tf32_rna(W[k][n]).
// W1: 128x256 at 0; W2: 256x256 at 32768; W3: 256x64 at 98304.
// ---------------------------------------------------------------------------
__global__ void wconv_kernel(const float* __restrict__ W1, const float* __restrict__ W2,
                             const float* __restrict__ W3, float* __restrict__ out)
{
    int idx = blockIdx.x * blockDim.x + threadIdx.x;
    const float* W; int K, Nw, local;
    if (idx < 32768)       { W = W1; K = 128; Nw = 256; local = idx; }
    else if (idx < 98304)  { W = W2; K = 256; Nw = 256; local = idx - 32768; }
    else if (idx < 114688) { W = W3; K = 256; Nw = 64;  local = idx - 98304; }
    else return;
    int n = local / K;
    int r = local - n * K;
    int t = r >> 5, kp = r & 31;
    int u = kp >> 3, m8 = kp & 7;          // k' = 8u + m8
    int k = t * 32 + u + 4 * m8;           // k_local = u + 4*m8
    out[idx] = __uint_as_float(f2tf32(W[k * Nw + n]));
}

// ---------------------------------------------------------------------------
// CSR build (parallel 3-stage scan)
// ---------------------------------------------------------------------------
__global__ void zero_count_kernel(int* __restrict__ count, int N)
{
    int i = blockIdx.x * blockDim.x + threadIdx.x;
    if (i < N) count[i] = 0;
}

__global__ void count_kernel(const int* __restrict__ ei, int E, int Etot,
                             int* __restrict__ count)
{
    int e = blockIdx.x * blockDim.x + threadIdx.x;
    if (e >= Etot) return;
    int dst = (e < E) ? __ldg(&ei[E + e]) : (e - E);
    atomicAdd(&count[dst], 1);
}

__global__ void scan_block_kernel(const int* __restrict__ count, int* __restrict__ excl,
                                  int* __restrict__ bsum, int N)
{
    __shared__ int sh[SCAN_BS];
    int t = threadIdx.x;
    int idx = blockIdx.x * SCAN_BS + t;
    int v = (idx < N) ? count[idx] : 0;
    sh[t] = v;
    __syncthreads();
#pragma unroll
    for (int o = 1; o < SCAN_BS; o <<= 1) {
        int add = (t >= o) ? sh[t - o] : 0;
        __syncthreads();
        sh[t] += add;
        __syncthreads();
    }
    if (idx < N) excl[idx] = sh[t] - v;
    if (t == SCAN_BS - 1) bsum[blockIdx.x] = sh[t];
}

__global__ void scan_sums_kernel(int* __restrict__ bsum, int nb)
{
    __shared__ int sh[256];
    int t = threadIdx.x;
    int v = (t < nb) ? bsum[t] : 0;
    sh[t] = v;
    __syncthreads();
#pragma unroll
    for (int o = 1; o < 256; o <<= 1) {
        int add = (t >= o) ? sh[t - o] : 0;
        __syncthreads();
        sh[t] += add;
        __syncthreads();
    }
    if (t < nb) bsum[t] = sh[t] - v;  // exclusive
}

__global__ void scan_finish_kernel(const int* __restrict__ excl, const int* __restrict__ bsum,
                                   int* __restrict__ ptr, int* __restrict__ cursor,
                                   int N, int Etot)
{
    int i = blockIdx.x * blockDim.x + threadIdx.x;
    if (i < N) {
        int p = excl[i] + bsum[i / SCAN_BS];
        ptr[i] = p;
        cursor[i] = p;
    }
    if (i == 0) ptr[N] = Etot;
}

__global__ void scatter_kernel(const int* __restrict__ ei, int E, int Etot,
                               int* __restrict__ cursor, int* __restrict__ csr)
{
    int e = blockIdx.x * blockDim.x + threadIdx.x;
    if (e >= Etot) return;
    int src, dst;
    if (e < E) { src = __ldg(&ei[e]); dst = __ldg(&ei[E + e]); }
    else       { src = dst = e - E; }
    int pos = atomicAdd(&cursor[dst], 1);
    csr[pos] = src;
}

// ---------------------------------------------------------------------------
// TF32 tensor-core GEMM, cp.async double-buffered, occupancy-first.
// Cb[M,N](bf16) = A[M,K] @ Wt'. BM=128, BN=64, warp tile 16x64 (MI=1),
// 256 threads, 3 CTAs/SM. B permuted-tf32 [n][K]; PERMA => A permuted too
// (LDS.128 frags, no cvt). Fused s/d attention-dot epilogue.
// ---------------------------------------------------------------------------
#define AS(b, m, k) sm[(b) * (128 * 36) + (m) * 36 + (k)]
#define BS(b, n, k) sm[9216 + (b) * (64 * 36) + (n) * 36 + (k)]

template <bool PERMA>
__global__ __launch_bounds__(256, 3) void mma_gemm_kernel(
    const float* __restrict__ A, const float* __restrict__ Bw,
    __nv_bfloat16* __restrict__ Cb, int M, int N, int K,
    const float* __restrict__ a_src, const float* __restrict__ a_dst,
    float* __restrict__ s_out, float* __restrict__ d_out, int H)
{
    constexpr int BM_ = 128, BK_ = 32;
    constexpr int AV = 4;   // A: 128*32/(256*4) 16B chunks per thread
    constexpr int BV = 2;   // B: 64*32/(256*4)

    extern __shared__ float sm[];

    const int tid = threadIdx.x;
    const int wid = tid >> 5;
    const int lane = tid & 31;
    const int g = lane >> 2;
    const int t4 = lane & 3;

    const int rowBase = blockIdx.y * BM_;
    const int colBase = blockIdx.x * 64;
    const int warp_m = wid * 16;

    auto issueTile = [&](int t, int b) {
        int k0 = t * BK_;
#pragma unroll
        for (int l = 0; l < AV; l++) {
            int c = tid + l * 256;
            int m = c >> 3;
            int cp = (c & 7) * 4;
            int row = rowBase + m;
            const float* src = A + (size_t)row * K + k0 + cp;
            uint32_t dst = (uint32_t)__cvta_generic_to_shared(&AS(b, m, cp));
            int sz = (row < M) ? 16 : 0;   // zfill OOB rows
            asm volatile("cp.async.cg.shared.global [%0], [%1], 16, %2;\n"
                         :: "r"(dst), "l"(src), "r"(sz));
        }
#pragma unroll
        for (int l = 0; l < BV; l++) {
            int c = tid + l * 256;
            int nloc = c >> 3;
            int cp = (c & 7) * 4;
            const float* src = Bw + (size_t)(colBase + nloc) * K + k0 + cp;
            uint32_t dst = (uint32_t)__cvta_generic_to_shared(&BS(b, nloc, cp));
            asm volatile("cp.async.cg.shared.global [%0], [%1], 16;\n"
                         :: "r"(dst), "l"(src));
        }
    };

    float acc[8][4];
#pragma unroll
    for (int ni = 0; ni < 8; ni++)
#pragma unroll
        for (int j = 0; j < 4; j++) acc[ni][j] = 0.f;

    const int tiles = K / BK_;
    issueTile(0, 0);
    asm volatile("cp.async.commit_group;\n" ::: "memory");

    for (int t = 0; t < tiles; t++) {
        int b = t & 1;
        if (t + 1 < tiles) {
            issueTile(t + 1, b ^ 1);
            asm volatile("cp.async.commit_group;\n" ::: "memory");
            asm volatile("cp.async.wait_group 1;\n" ::: "memory");
        } else {
            asm volatile("cp.async.wait_group 0;\n" ::: "memory");
        }
        __syncthreads();

#pragma unroll
        for (int half = 0; half < 2; half++) {
            uint32_t afr[2][4];   // [k2][frag]
            if (PERMA) {
                int m = warp_m;
                uint4 v0 = *(const uint4*)&AS(b, m + g,     8 * t4 + 4 * half);
                uint4 v1 = *(const uint4*)&AS(b, m + 8 + g, 8 * t4 + 4 * half);
                afr[0][0] = v0.x; afr[0][1] = v1.x; afr[0][2] = v0.y; afr[0][3] = v1.y;
                afr[1][0] = v0.z; afr[1][1] = v1.z; afr[1][2] = v0.w; afr[1][3] = v1.w;
            } else {
#pragma unroll
                for (int k2 = 0; k2 < 2; k2++) {
                    int kk = half * 2 + k2;
                    int m = warp_m;
                    afr[k2][0] = f2tf32(AS(b, m + g,     kk * 8 + t4));
                    afr[k2][1] = f2tf32(AS(b, m + 8 + g, kk * 8 + t4));
                    afr[k2][2] = f2tf32(AS(b, m + g,     kk * 8 + t4 + 4));
                    afr[k2][3] = f2tf32(AS(b, m + 8 + g, kk * 8 + t4 + 4));
                }
            }
#pragma unroll
            for (int nh = 0; nh < 2; nh++) {
                uint32_t bq[4][4];
#pragma unroll
                for (int i = 0; i < 4; i++) {
                    uint4 v = *(const uint4*)&BS(b, (nh * 4 + i) * 8 + g,
                                                 8 * t4 + 4 * half);
                    bq[i][0] = v.x; bq[i][1] = v.y; bq[i][2] = v.z; bq[i][3] = v.w;
                }
#pragma unroll
                for (int k2 = 0; k2 < 2; k2++)
#pragma unroll
                    for (int i = 0; i < 4; i++) {
                        uint32_t bf[2] = { bq[i][2 * k2], bq[i][2 * k2 + 1] };
                        mma_tf32(acc[nh * 4 + i], afr[k2], bf);
                    }
            }
        }
        __syncthreads();
    }

    // ---- Epilogue: bf16 C store (natural order) + fused attention dots ----
    const int head = colBase >> 6;
    const float* ah = a_src + head * 64;
    const float* dh = a_dst + head * 64;
    float2 av[8], dv[8];
#pragma unroll
    for (int ni = 0; ni < 8; ni++) {
        av[ni] = *(const float2*)&ah[ni * 8 + 2 * t4];
        dv[ni] = *(const float2*)&dh[ni * 8 + 2 * t4];
    }

    {
        int r0 = rowBase + warp_m + g;
        int r1 = r0 + 8;
        float s0 = 0.f, s1 = 0.f, d0 = 0.f, d1 = 0.f;
#pragma unroll
        for (int ni = 0; ni < 8; ni++) {
            float c0 = acc[ni][0], c1 = acc[ni][1];
            float c2 = acc[ni][2], c3 = acc[ni][3];
            int col = colBase + ni * 8 + 2 * t4;
            if (r0 < M) *(__nv_bfloat162*)&Cb[(size_t)r0 * N + col] = __floats2bfloat162_rn(c0, c1);
            if (r1 < M) *(__nv_bfloat162*)&Cb[(size_t)r1 * N + col] = __floats2bfloat162_rn(c2, c3);
            s0 += c0 * av[ni].x + c1 * av[ni].y;
            s1 += c2 * av[ni].x + c3 * av[ni].y;
            d0 += c0 * dv[ni].x + c1 * dv[ni].y;
            d1 += c2 * dv[ni].x + c3 * dv[ni].y;
        }
#pragma unroll
        for (int o = 1; o <= 2; o <<= 1) {
            s0 += __shfl_xor_sync(0xffffffffu, s0, o);
            s1 += __shfl_xor_sync(0xffffffffu, s1, o);
            d0 += __shfl_xor_sync(0xffffffffu, d0, o);
            d1 += __shfl_xor_sync(0xffffffffu, d1, o);
        }
        if (t4 == 0) {
            if (r0 < M) { s_out[r0 * H + head] = s0; d_out[r0 * H + head] = d0; }
            if (r1 < M) { s_out[r1 * H + head] = s1; d_out[r1 * H + head] = d1; }
        }
    }
}

// ---------------------------------------------------------------------------
// Single-pass fused GAT (H=4): one warp per destination node, pipelined.
// Output written in PERMUTED tf32-rounded layout (feeds next GEMM as A).
// ---------------------------------------------------------------------------
__global__ __launch_bounds__(256) void gat_h4_kernel(
    const int* __restrict__ ptr, const int* __restrict__ csr,
    const float* __restrict__ s, const float* __restrict__ dco,
    const __nv_bfloat16* __restrict__ xpb, const float* __restrict__ bias,
    float* __restrict__ out, int N)
{
    constexpr int F = 256;
    int warp = (blockIdx.x * blockDim.x + threadIdx.x) >> 5;
    int lane = threadIdx.x & 31;
    if (warp >= N) return;
    int n = warp;
    int beg = __ldg(&ptr[n]);
    int end = __ldg(&ptr[n + 1]);

    const int myh = lane >> 3;
    const float dmy = __ldg(&dco[n * 4 + myh]);

    float acc[8];
#pragma unroll
    for (int j = 0; j < 8; j++) acc[j] = 0.f;
    float den = 0.f;

    int   srcs[4];
    float svs[4];
    auto loadMeta = [&](int base) {
#pragma unroll
        for (int b = 0; b < 4; b++) {
            int idx = base + b;
            srcs[b] = __ldg(&csr[idx < end ? idx : end - 1]);
        }
#pragma unroll
        for (int b = 0; b < 4; b++)
            svs[b] = __ldg(&s[srcs[b] * 4 + myh]);
    };

    loadMeta(beg);
    for (int base = beg; base < end; base += 4) {
        int   csrc[4];
        float csv[4];
#pragma unroll
        for (int b = 0; b < 4; b++) { csrc[b] = srcs[b]; csv[b] = svs[b]; }
        if (base + 4 < end) loadMeta(base + 4);

#pragma unroll
        for (int b = 0; b < 4; b++) {
            if (base + b < end) {
                float e = csv[b] + dmy;
                e = e > 0.f ? e : NEG_SLOPE * e;
                float w = __expf(e);
                den += w;
                uint4 v = __ldg((const uint4*)(xpb + (size_t)csrc[b] * F) + lane);
                float2 f0 = __bfloat1622float2(*(__nv_bfloat162*)&v.x);
                float2 f1 = __bfloat1622float2(*(__nv_bfloat162*)&v.y);
                float2 f2 = __bfloat1622float2(*(__nv_bfloat162*)&v.z);
                float2 f3 = __bfloat1622float2(*(__nv_bfloat162*)&v.w);
                acc[0] += w * f0.x; acc[1] += w * f0.y;
                acc[2] += w * f1.x; acc[3] += w * f1.y;
                acc[4] += w * f2.x; acc[5] += w * f2.y;
                acc[6] += w * f3.x; acc[7] += w * f3.y;
            }
        }
    }

    const float iv = 1.f / (den + 1e-16f);
#pragma unroll
    for (int j = 0; j < 8; j++) {
        float v = acc[j] * iv + __ldg(&bias[lane * 8 + j]);
        acc[j] = v > 0.f ? v : 0.f;
    }
    // Permuted tf32-rounded store: element k = lane*8 + j lands at
    // (lane>>2)*32 + 8*(j%4) + 2*(lane&3) + (j>>2); pairs (j, j+4) adjacent.
    float* orow = out + (size_t)n * F + (lane >> 2) * 32 + 2 * (lane & 3);
#pragma unroll
    for (int j = 0; j < 4; j++) {
        float2 v = make_float2(__uint_as_float(f2tf32(acc[j])),
                               __uint_as_float(f2tf32(acc[j + 4])));
        *(float2*)&orow[8 * j] = v;
    }
}

// ---------------------------------------------------------------------------
// Single-pass fused GAT (H=1) + final FC (64->10): writes logits directly.
// ---------------------------------------------------------------------------
__global__ __launch_bounds__(256) void gat_h1_fc_kernel(
    const int* __restrict__ ptr, const int* __restrict__ csr,
    const float* __restrict__ s, const float* __restrict__ dco,
    const __nv_bfloat16* __restrict__ xpb, const float* __restrict__ bias,
    const float* __restrict__ Wfc, const float* __restrict__ bfc,
    float* __restrict__ out, int N)
{
    constexpr int F = 64;
    __shared__ float Wt[10][64];
    for (int i = threadIdx.x; i < 640; i += blockDim.x) {
        int k = i / 10, j = i - k * 10;
        Wt[j][k] = __ldg(&Wfc[i]);
    }
    __syncthreads();

    int warp = (blockIdx.x * blockDim.x + threadIdx.x) >> 5;
    int lane = threadIdx.x & 31;
    if (warp >= N) return;
    int n = warp;
    int beg = __ldg(&ptr[n]);
    int end = __ldg(&ptr[n + 1]);

    const float dmy = __ldg(&dco[n]);

    float a0 = 0.f, a1 = 0.f, den = 0.f;

    int   srcs[4];
    float svs[4];
    auto loadMeta = [&](int base) {
#pragma unroll
        for (int b = 0; b < 4; b++) {
            int idx = base + b;
            srcs[b] = __ldg(&csr[idx < end ? idx : end - 1]);
        }
#pragma unroll
        for (int b = 0; b < 4; b++)
            svs[b] = __ldg(&s[srcs[b]]);
    };

    loadMeta(beg);
    for (int base = beg; base < end; base += 4) {
        int   csrc[4];
        float csv[4];
#pragma unroll
        for (int b = 0; b < 4; b++) { csrc[b] = srcs[b]; csv[b] = svs[b]; }
        if (base + 4 < end) loadMeta(base + 4);

#pragma unroll
        for (int b = 0; b < 4; b++) {
            if (base + b < end) {
                float e = csv[b] + dmy;
                e = e > 0.f ? e : NEG_SLOPE * e;
                float w = __expf(e);
                den += w;
                uint32_t v = __ldg((const uint32_t*)(xpb + (size_t)csrc[b] * F) + lane);
                float2 f = __bfloat1622float2(*(__nv_bfloat162*)&v);
                a0 += w * f.x;
                a1 += w * f.y;
            }
        }
    }

    const float iv = 1.f / (den + 1e-16f);
    float h0 = a0 * iv + __ldg(&bias[2 * lane]);
    float h1 = a1 * iv + __ldg(&bias[2 * lane + 1]);
    h0 = h0 > 0.f ? h0 : 0.f;
    h1 = h1 > 0.f ? h1 : 0.f;

    float p[10];
#pragma unroll
    for (int j = 0; j < 10; j++)
        p[j] = h0 * Wt[j][2 * lane] + h1 * Wt[j][2 * lane + 1];
#pragma unroll
    for (int o = 16; o > 0; o >>= 1)
#pragma unroll
        for (int j = 0; j < 10; j++)
            p[j] += __shfl_xor_sync(0xffffffffu, p[j], o);

    if (lane < 10)
        out[n * 10 + lane] = p[lane] + __ldg(&bfc[lane]);
}

// ---------------------------------------------------------------------------
// Orchestration
// ---------------------------------------------------------------------------
extern "C" void kernel_launch(void* const* d_in, const int* in_sizes, int n_in,
                              void* d_out, int out_size)
{
    const float* x    = (const float*)d_in[0];
    const int*   ei   = (const int*)d_in[1];
    const float* W1   = (const float*)d_in[2];
    const float* as1  = (const float*)d_in[3];
    const float* ad1  = (const float*)d_in[4];
    const float* b1   = (const float*)d_in[5];
    const float* W2   = (const float*)d_in[6];
    const float* as2  = (const float*)d_in[7];
    const float* ad2  = (const float*)d_in[8];
    const float* b2   = (const float*)d_in[9];
    const float* W3   = (const float*)d_in[10];
    const float* as3  = (const float*)d_in[11];
    const float* ad3  = (const float*)d_in[12];
    const float* b3   = (const float*)d_in[13];
    const float* Wfc  = (const float*)d_in[14];
    const float* bfc  = (const float*)d_in[15];
    float* out = (float*)d_out;

    int N = in_sizes[0] / 128;
    int E = in_sizes[1] / 2;
    int Etot = E + N;

    float *bufB, *s, *d, *wtf;
    __nv_bfloat16* xpb;
    int *count, *excl, *cursor, *ptr, *bsum, *csr;
    cudaGetSymbolAddress((void**)&bufB, g_bufB);
    cudaGetSymbolAddress((void**)&xpb, g_xpb);
    cudaGetSymbolAddress((void**)&wtf, g_wtf);
    cudaGetSymbolAddress((void**)&s, g_s);
    cudaGetSymbolAddress((void**)&d, g_d);
    cudaGetSymbolAddress((void**)&count, g_count);
    cudaGetSymbolAddress((void**)&excl, g_excl);
    cudaGetSymbolAddress((void**)&cursor, g_cursor);
    cudaGetSymbolAddress((void**)&ptr, g_ptr);
    cudaGetSymbolAddress((void**)&bsum, g_bsum);
    cudaGetSymbolAddress((void**)&csr, g_csr);

    // dynamic smem: A 2x128x36 fl + B 2x64x36 fl = 55296 B (3 CTAs/SM)
    const int smemB = (2 * 128 * 36 + 2 * 64 * 36) * 4;
    cudaFuncSetAttribute(mma_gemm_kernel<false>,
                         cudaFuncAttributeMaxDynamicSharedMemorySize, smemB);
    cudaFuncSetAttribute(mma_gemm_kernel<true>,
                         cudaFuncAttributeMaxDynamicSharedMemorySize, smemB);

    int nb = ceil_div(N, SCAN_BS);
    int rowBlocks = ceil_div(N, 128);

    // Launch order: index 3 = layer-1 GEMM (profiler window).
    wconv_kernel<<<448, 256>>>(W1, W2, W3, wtf);                                    // 0
    zero_count_kernel<<<ceil_div(N, 256), 256>>>(count, N);                         // 1
    count_kernel<<<ceil_div(Etot, 256), 256>>>(ei, E, Etot, count);                 // 2
    mma_gemm_kernel<false><<<dim3(4, rowBlocks), 256, smemB>>>(                     // 3
        x, wtf, xpb, N, 256, 128, as1, ad1, s, d, 4);
    scan_block_kernel<<<nb, SCAN_BS>>>(count, excl, bsum, N);                       // 4
    scan_sums_kernel<<<1, 256>>>(bsum, nb);                                         // 5
    scan_finish_kernel<<<ceil_div(N, 256), 256>>>(excl, bsum, ptr, cursor, N, Etot);// 6
    scatter_kernel<<<ceil_div(Etot, 256), 256>>>(ei, E, Etot, cursor, csr);         // 7

    // --- Layer 1 gather (writes permuted tf32 bufB) ---
    gat_h4_kernel<<<ceil_div(N * 32, 256), 256>>>(ptr, csr, s, d, xpb, b1, bufB, N);

    // --- Layer 2: 256 -> (4,64), permuted-A fast path ---
    mma_gemm_kernel<true><<<dim3(4, rowBlocks), 256, smemB>>>(
        bufB, wtf + 32768, xpb, N, 256, 256, as2, ad2, s, d, 4);
    gat_h4_kernel<<<ceil_div(N * 32, 256), 256>>>(ptr, csr, s, d, xpb, b2, bufB, N);

    // --- Layer 3: 256 -> (1,64), permuted-A fast path + FC fused ---
    mma_gemm_kernel<true><<<dim3(1, rowBlocks), 256, smemB>>>(
        bufB, wtf + 98304, xpb, N, 64, 256, as3, ad3, s, d, 1);
    gat_h1_fc_kernel<<<ceil_div(N * 32, 256), 256>>>(ptr, csr, s, d, xpb, b3,
                                                     Wfc, bfc, out, N);
}

// round 15
// speedup vs baseline: 1.0449x; 1.0449x over previous
#include <cuda_runtime.h>
#include <cuda_bf16.h>
#include <math.h>
#include <stdint.h>

// ---------------------------------------------------------------------------
// GAT: 3 layers (H=4,C=64) -> (H=4,C=64) -> (H=1,C=64) -> FC 64->10
// N=50000 nodes, E=800000 edges (+N self loops)
// R15: R12 kernels (measured best) + graph-forked side stream so the CSR
// build runs CONCURRENTLY with the layer-1 GEMM (independent work).
// ---------------------------------------------------------------------------

#define MAX_N 50000
#define MAX_E 800000
#define MAX_ETOT (MAX_E + MAX_N)
#define NEG_SLOPE 0.2f
#define SCAN_BS 512

// Scratch (static __device__ globals; allocation-free)
__device__ float          g_bufB[MAX_N * 256];   // fp32 activations (layer I/O)
__device__ __nv_bfloat16  g_xpb[MAX_N * 256];    // bf16 transformed features
__device__ float g_s[MAX_N * 4];
__device__ float g_d[MAX_N * 4];
__device__ int   g_count[MAX_N];
__device__ int   g_excl[MAX_N];
__device__ int   g_cursor[MAX_N];
__device__ int   g_ptr[MAX_N + 1];
__device__ int   g_bsum[256];
__device__ int   g_csr[MAX_ETOT];

static inline int ceil_div(int a, int b) { return (a + b - 1) / b; }

// ---------------------------------------------------------------------------
// CSR build (parallel 3-stage scan)
// ---------------------------------------------------------------------------
__global__ void zero_count_kernel(int* __restrict__ count, int N)
{
    int i = blockIdx.x * blockDim.x + threadIdx.x;
    if (i < N) count[i] = 0;
}

__global__ void count_kernel(const int* __restrict__ ei, int E, int Etot,
                             int* __restrict__ count)
{
    int e = blockIdx.x * blockDim.x + threadIdx.x;
    if (e >= Etot) return;
    int dst = (e < E) ? __ldg(&ei[E + e]) : (e - E);
    atomicAdd(&count[dst], 1);
}

__global__ void scan_block_kernel(const int* __restrict__ count, int* __restrict__ excl,
                                  int* __restrict__ bsum, int N)
{
    __shared__ int sh[SCAN_BS];
    int t = threadIdx.x;
    int idx = blockIdx.x * SCAN_BS + t;
    int v = (idx < N) ? count[idx] : 0;
    sh[t] = v;
    __syncthreads();
#pragma unroll
    for (int o = 1; o < SCAN_BS; o <<= 1) {
        int add = (t >= o) ? sh[t - o] : 0;
        __syncthreads();
        sh[t] += add;
        __syncthreads();
    }
    if (idx < N) excl[idx] = sh[t] - v;
    if (t == SCAN_BS - 1) bsum[blockIdx.x] = sh[t];
}

__global__ void scan_sums_kernel(int* __restrict__ bsum, int nb)
{
    __shared__ int sh[256];
    int t = threadIdx.x;
    int v = (t < nb) ? bsum[t] : 0;
    sh[t] = v;
    __syncthreads();
#pragma unroll
    for (int o = 1; o < 256; o <<= 1) {
        int add = (t >= o) ? sh[t - o] : 0;
        __syncthreads();
        sh[t] += add;
        __syncthreads();
    }
    if (t < nb) bsum[t] = sh[t] - v;  // exclusive
}

__global__ void scan_finish_kernel(const int* __restrict__ excl, const int* __restrict__ bsum,
                                   int* __restrict__ ptr, int* __restrict__ cursor,
                                   int N, int Etot)
{
    int i = blockIdx.x * blockDim.x + threadIdx.x;
    if (i < N) {
        int p = excl[i] + bsum[i / SCAN_BS];
        ptr[i] = p;
        cursor[i] = p;
    }
    if (i == 0) ptr[N] = Etot;
}

__global__ void scatter_kernel(const int* __restrict__ ei, int E, int Etot,
                               int* __restrict__ cursor, int* __restrict__ csr)
{
    int e = blockIdx.x * blockDim.x + threadIdx.x;
    if (e >= Etot) return;
    int src, dst;
    if (e < E) { src = __ldg(&ei[e]); dst = __ldg(&ei[E + e]); }
    else       { src = dst = e - E; }
    int pos = atomicAdd(&cursor[dst], 1);
    csr[pos] = src;
}

// ---------------------------------------------------------------------------
// TF32 helpers
// ---------------------------------------------------------------------------
__device__ __forceinline__ uint32_t f2tf32(float f)
{
    uint32_t o;
    asm("cvt.rna.tf32.f32 %0, %1;" : "=r"(o) : "f"(f));
    return o;
}

__device__ __forceinline__ void mma_tf32(float* c, const uint32_t* a, const uint32_t* b)
{
    asm volatile(
        "mma.sync.aligned.m16n8k8.row.col.f32.tf32.tf32.f32 "
        "{%0,%1,%2,%3}, {%4,%5,%6,%7}, {%8,%9}, {%0,%1,%2,%3};\n"
        : "+f"(c[0]), "+f"(c[1]), "+f"(c[2]), "+f"(c[3])
        : "r"(a[0]), "r"(a[1]), "r"(a[2]), "r"(a[3]), "r"(b[0]), "r"(b[1]));
}

// ---------------------------------------------------------------------------
// TF32 tensor-core GEMM, cp.async double-buffered (R12 configuration):
// Cb[M,N](bf16) = A[M,K] @ B[K,N], fp32 in, tf32 cvt at fragment read.
// BM=128, BK=32, 256 threads, 2 CTAs/SM. Fused s/d attention-dot epilogue.
// ---------------------------------------------------------------------------
#define APAD 36
#define AS(b, m, k) sm[(b) * (128 * APAD) + (m) * APAD + (k)]
#define BS(b, r, c) sm[2 * 128 * APAD + (b) * (32 * (BN_ + 8)) + (r) * (BN_ + 8) + (c)]

template <int BN_>
__global__ __launch_bounds__(256, 2) void mma_gemm_kernel(
    const float* __restrict__ A, const float* __restrict__ B,
    __nv_bfloat16* __restrict__ Cb, int M, int N, int K,
    const float* __restrict__ a_src, const float* __restrict__ a_dst,
    float* __restrict__ s_out, float* __restrict__ d_out, int H)
{
    constexpr int BM_ = 128, BK_ = 32;
    constexpr int MI = (BN_ == 128) ? 2 : 1;
    constexpr int AV = 4;
    constexpr int BV = (BK_ * BN_) / 1024;

    extern __shared__ float sm[];

    const int tid = threadIdx.x;
    const int wid = tid >> 5;
    const int lane = tid & 31;
    const int g = lane >> 2;
    const int t4 = lane & 3;

    const int rowBase = blockIdx.y * BM_;
    const int colBase = blockIdx.x * BN_;
    const int warp_m = (BN_ == 128) ? (wid >> 1) * 32 : wid * 16;
    const int warp_n = (BN_ == 128) ? (wid & 1) * 64 : 0;

    auto issueTile = [&](int t, int b) {
        int k0 = t * BK_;
#pragma unroll
        for (int l = 0; l < AV; l++) {
            int li = tid + l * 256;
            int m = li >> 3;
            int k4 = (li & 7) * 4;
            int row = rowBase + m;
            const float* src = A + (size_t)row * K + k0 + k4;
            uint32_t dst = (uint32_t)__cvta_generic_to_shared(&AS(b, m, k4));
            int sz = (row < M) ? 16 : 0;   // zfill OOB rows
            asm volatile("cp.async.cg.shared.global [%0], [%1], 16, %2;\n"
                         :: "r"(dst), "l"(src), "r"(sz));
        }
#pragma unroll
        for (int l = 0; l < BV; l++) {
            int li = tid + l * 256;
            int r = li / (BN_ / 4);
            int c4 = (li % (BN_ / 4)) * 4;
            const float* src = B + (size_t)(k0 + r) * N + colBase + c4;
            uint32_t dst = (uint32_t)__cvta_generic_to_shared(&BS(b, r, c4));
            asm volatile("cp.async.cg.shared.global [%0], [%1], 16;\n"
                         :: "r"(dst), "l"(src));
        }
    };

    float acc[MI][8][4];
#pragma unroll
    for (int mi = 0; mi < MI; mi++)
#pragma unroll
        for (int ni = 0; ni < 8; ni++)
#pragma unroll
            for (int j = 0; j < 4; j++) acc[mi][ni][j] = 0.f;

    const int tiles = K / BK_;
    issueTile(0, 0);
    asm volatile("cp.async.commit_group;\n" ::: "memory");

    for (int t = 0; t < tiles; t++) {
        int b = t & 1;
        if (t + 1 < tiles) {
            issueTile(t + 1, b ^ 1);
            asm volatile("cp.async.commit_group;\n" ::: "memory");
            asm volatile("cp.async.wait_group 1;\n" ::: "memory");
        } else {
            asm volatile("cp.async.wait_group 0;\n" ::: "memory");
        }
        __syncthreads();

#pragma unroll
        for (int kk = 0; kk < BK_ / 8; kk++) {
            uint32_t af[MI][4], bf[8][2];
#pragma unroll
            for (int mi = 0; mi < MI; mi++) {
                int m = warp_m + mi * 16;
                af[mi][0] = f2tf32(AS(b, m + g,     kk * 8 + t4));
                af[mi][1] = f2tf32(AS(b, m + 8 + g, kk * 8 + t4));
                af[mi][2] = f2tf32(AS(b, m + g,     kk * 8 + t4 + 4));
                af[mi][3] = f2tf32(AS(b, m + 8 + g, kk * 8 + t4 + 4));
            }
#pragma unroll
            for (int ni = 0; ni < 8; ni++) {
                int n = warp_n + ni * 8 + g;
                bf[ni][0] = f2tf32(BS(b, kk * 8 + t4,     n));
                bf[ni][1] = f2tf32(BS(b, kk * 8 + t4 + 4, n));
            }
#pragma unroll
            for (int mi = 0; mi < MI; mi++)
#pragma unroll
                for (int ni = 0; ni < 8; ni++)
                    mma_tf32(acc[mi][ni], af[mi], bf[ni]);
        }
        __syncthreads();
    }

    // ---- Epilogue: bf16 C store + fused attention coefficients (fp32 accs) ----
    const int head = (colBase + warp_n) >> 6;
    const float* ah = a_src + head * 64;
    const float* dh = a_dst + head * 64;
    float2 av[8], dv[8];
#pragma unroll
    for (int ni = 0; ni < 8; ni++) {
        av[ni] = *(const float2*)&ah[ni * 8 + 2 * t4];
        dv[ni] = *(const float2*)&dh[ni * 8 + 2 * t4];
    }

#pragma unroll
    for (int mi = 0; mi < MI; mi++) {
        int r0 = rowBase + warp_m + mi * 16 + g;
        int r1 = r0 + 8;
        float s0 = 0.f, s1 = 0.f, d0 = 0.f, d1 = 0.f;
#pragma unroll
        for (int ni = 0; ni < 8; ni++) {
            float c0 = acc[mi][ni][0], c1 = acc[mi][ni][1];
            float c2 = acc[mi][ni][2], c3 = acc[mi][ni][3];
            int col = colBase + warp_n + ni * 8 + 2 * t4;
            if (r0 < M) *(__nv_bfloat162*)&Cb[(size_t)r0 * N + col] = __floats2bfloat162_rn(c0, c1);
            if (r1 < M) *(__nv_bfloat162*)&Cb[(size_t)r1 * N + col] = __floats2bfloat162_rn(c2, c3);
            s0 += c0 * av[ni].x + c1 * av[ni].y;
            s1 += c2 * av[ni].x + c3 * av[ni].y;
            d0 += c0 * dv[ni].x + c1 * dv[ni].y;
            d1 += c2 * dv[ni].x + c3 * dv[ni].y;
        }
#pragma unroll
        for (int o = 1; o <= 2; o <<= 1) {
            s0 += __shfl_xor_sync(0xffffffffu, s0, o);
            s1 += __shfl_xor_sync(0xffffffffu, s1, o);
            d0 += __shfl_xor_sync(0xffffffffu, d0, o);
            d1 += __shfl_xor_sync(0xffffffffu, d1, o);
        }
        if (t4 == 0) {
            if (r0 < M) { s_out[r0 * H + head] = s0; d_out[r0 * H + head] = d0; }
            if (r1 < M) { s_out[r1 * H + head] = s1; d_out[r1 * H + head] = d1; }
        }
    }
}

// ---------------------------------------------------------------------------
// Single-pass fused GAT (H=4): one warp per destination node, pipelined.
// ---------------------------------------------------------------------------
__global__ __launch_bounds__(256) void gat_h4_kernel(
    const int* __restrict__ ptr, const int* __restrict__ csr,
    const float* __restrict__ s, const float* __restrict__ dco,
    const __nv_bfloat16* __restrict__ xpb, const float* __restrict__ bias,
    float* __restrict__ out, int N)
{
    constexpr int F = 256;
    int warp = (blockIdx.x * blockDim.x + threadIdx.x) >> 5;
    int lane = threadIdx.x & 31;
    if (warp >= N) return;
    int n = warp;
    int beg = __ldg(&ptr[n]);
    int end = __ldg(&ptr[n + 1]);

    const int myh = lane >> 3;
    const float dmy = __ldg(&dco[n * 4 + myh]);

    float acc[8];
#pragma unroll
    for (int j = 0; j < 8; j++) acc[j] = 0.f;
    float den = 0.f;

    int   srcs[4];
    float svs[4];
    auto loadMeta = [&](int base) {
#pragma unroll
        for (int b = 0; b < 4; b++) {
            int idx = base + b;
            srcs[b] = __ldg(&csr[idx < end ? idx : end - 1]);
        }
#pragma unroll
        for (int b = 0; b < 4; b++)
            svs[b] = __ldg(&s[srcs[b] * 4 + myh]);
    };

    loadMeta(beg);
    for (int base = beg; base < end; base += 4) {
        int   csrc[4];
        float csv[4];
#pragma unroll
        for (int b = 0; b < 4; b++) { csrc[b] = srcs[b]; csv[b] = svs[b]; }
        if (base + 4 < end) loadMeta(base + 4);

#pragma unroll
        for (int b = 0; b < 4; b++) {
            if (base + b < end) {
                float e = csv[b] + dmy;
                e = e > 0.f ? e : NEG_SLOPE * e;
                float w = __expf(e);
                den += w;
                uint4 v = __ldg((const uint4*)(xpb + (size_t)csrc[b] * F) + lane);
                float2 f0 = __bfloat1622float2(*(__nv_bfloat162*)&v.x);
                float2 f1 = __bfloat1622float2(*(__nv_bfloat162*)&v.y);
                float2 f2 = __bfloat1622float2(*(__nv_bfloat162*)&v.z);
                float2 f3 = __bfloat1622float2(*(__nv_bfloat162*)&v.w);
                acc[0] += w * f0.x; acc[1] += w * f0.y;
                acc[2] += w * f1.x; acc[3] += w * f1.y;
                acc[4] += w * f2.x; acc[5] += w * f2.y;
                acc[6] += w * f3.x; acc[7] += w * f3.y;
            }
        }
    }

    const float iv = 1.f / (den + 1e-16f);
#pragma unroll
    for (int j = 0; j < 8; j++) {
        float v = acc[j] * iv + __ldg(&bias[lane * 8 + j]);
        acc[j] = v > 0.f ? v : 0.f;
    }
    float4* orow = (float4*)(out + (size_t)n * F);
    orow[lane * 2]     = make_float4(acc[0], acc[1], acc[2], acc[3]);
    orow[lane * 2 + 1] = make_float4(acc[4], acc[5], acc[6], acc[7]);
}

// ---------------------------------------------------------------------------
// Single-pass fused GAT (H=1) + final FC (64->10): writes logits directly.
// ---------------------------------------------------------------------------
__global__ __launch_bounds__(256) void gat_h1_fc_kernel(
    const int* __restrict__ ptr, const int* __restrict__ csr,
    const float* __restrict__ s, const float* __restrict__ dco,
    const __nv_bfloat16* __restrict__ xpb, const float* __restrict__ bias,
    const float* __restrict__ Wfc, const float* __restrict__ bfc,
    float* __restrict__ out, int N)
{
    constexpr int F = 64;
    __shared__ float Wt[10][64];
    for (int i = threadIdx.x; i < 640; i += blockDim.x) {
        int k = i / 10, j = i - k * 10;
        Wt[j][k] = __ldg(&Wfc[i]);
    }
    __syncthreads();

    int warp = (blockIdx.x * blockDim.x + threadIdx.x) >> 5;
    int lane = threadIdx.x & 31;
    if (warp >= N) return;
    int n = warp;
    int beg = __ldg(&ptr[n]);
    int end = __ldg(&ptr[n + 1]);

    const float dmy = __ldg(&dco[n]);

    float a0 = 0.f, a1 = 0.f, den = 0.f;

    int   srcs[4];
    float svs[4];
    auto loadMeta = [&](int base) {
#pragma unroll
        for (int b = 0; b < 4; b++) {
            int idx = base + b;
            srcs[b] = __ldg(&csr[idx < end ? idx : end - 1]);
        }
#pragma unroll
        for (int b = 0; b < 4; b++)
            svs[b] = __ldg(&s[srcs[b]]);
    };

    loadMeta(beg);
    for (int base = beg; base < end; base += 4) {
        int   csrc[4];
        float csv[4];
#pragma unroll
        for (int b = 0; b < 4; b++) { csrc[b] = srcs[b]; csv[b] = svs[b]; }
        if (base + 4 < end) loadMeta(base + 4);

#pragma unroll
        for (int b = 0; b < 4; b++) {
            if (base + b < end) {
                float e = csv[b] + dmy;
                e = e > 0.f ? e : NEG_SLOPE * e;
                float w = __expf(e);
                den += w;
                uint32_t v = __ldg((const uint32_t*)(xpb + (size_t)csrc[b] * F) + lane);
                float2 f = __bfloat1622float2(*(__nv_bfloat162*)&v);
                a0 += w * f.x;
                a1 += w * f.y;
            }
        }
    }

    const float iv = 1.f / (den + 1e-16f);
    float h0 = a0 * iv + __ldg(&bias[2 * lane]);
    float h1 = a1 * iv + __ldg(&bias[2 * lane + 1]);
    h0 = h0 > 0.f ? h0 : 0.f;
    h1 = h1 > 0.f ? h1 : 0.f;

    float p[10];
#pragma unroll
    for (int j = 0; j < 10; j++)
        p[j] = h0 * Wt[j][2 * lane] + h1 * Wt[j][2 * lane + 1];
#pragma unroll
    for (int o = 16; o > 0; o >>= 1)
#pragma unroll
        for (int j = 0; j < 10; j++)
            p[j] += __shfl_xor_sync(0xffffffffu, p[j], o);

    if (lane < 10)
        out[n * 10 + lane] = p[lane] + __ldg(&bfc[lane]);
}

// ---------------------------------------------------------------------------
// Orchestration: fork CSR build onto a side stream, overlapping with GEMM1.
// Event fork/join is the standard stream-capture branching pattern (no syncs,
// no allocations of device memory).
// ---------------------------------------------------------------------------
extern "C" void kernel_launch(void* const* d_in, const int* in_sizes, int n_in,
                              void* d_out, int out_size)
{
    const float* x    = (const float*)d_in[0];
    const int*   ei   = (const int*)d_in[1];
    const float* W1   = (const float*)d_in[2];
    const float* as1  = (const float*)d_in[3];
    const float* ad1  = (const float*)d_in[4];
    const float* b1   = (const float*)d_in[5];
    const float* W2   = (const float*)d_in[6];
    const float* as2  = (const float*)d_in[7];
    const float* ad2  = (const float*)d_in[8];
    const float* b2   = (const float*)d_in[9];
    const float* W3   = (const float*)d_in[10];
    const float* as3  = (const float*)d_in[11];
    const float* ad3  = (const float*)d_in[12];
    const float* b3   = (const float*)d_in[13];
    const float* Wfc  = (const float*)d_in[14];
    const float* bfc  = (const float*)d_in[15];
    float* out = (float*)d_out;

    int N = in_sizes[0] / 128;
    int E = in_sizes[1] / 2;
    int Etot = E + N;

    float *bufB, *s, *d;
    __nv_bfloat16* xpb;
    int *count, *excl, *cursor, *ptr, *bsum, *csr;
    cudaGetSymbolAddress((void**)&bufB, g_bufB);
    cudaGetSymbolAddress((void**)&xpb, g_xpb);
    cudaGetSymbolAddress((void**)&s, g_s);
    cudaGetSymbolAddress((void**)&d, g_d);
    cudaGetSymbolAddress((void**)&count, g_count);
    cudaGetSymbolAddress((void**)&excl, g_excl);
    cudaGetSymbolAddress((void**)&cursor, g_cursor);
    cudaGetSymbolAddress((void**)&ptr, g_ptr);
    cudaGetSymbolAddress((void**)&bsum, g_bsum);
    cudaGetSymbolAddress((void**)&csr, g_csr);

    // dynamic smem: double-buffered A (128xAPAD fl) + B (32x(BN+8) fl)
    const int smem128 = (2 * 128 * APAD + 2 * 32 * (128 + 8)) * 4;  // 71680 B
    const int smem64  = (2 * 128 * APAD + 2 * 32 * (64 + 8))  * 4;  // 55296 B
    cudaFuncSetAttribute(mma_gemm_kernel<128>,
                         cudaFuncAttributeMaxDynamicSharedMemorySize, smem128);
    cudaFuncSetAttribute(mma_gemm_kernel<64>,
                         cudaFuncAttributeMaxDynamicSharedMemorySize, smem64);

    int nb = ceil_div(N, SCAN_BS);

    // Fork: side stream runs the CSR build concurrently with GEMM1 (main).
    cudaStream_t side;
    cudaStreamCreateWithFlags(&side, cudaStreamNonBlocking);
    cudaEvent_t evFork, evJoin;
    cudaEventCreateWithFlags(&evFork, cudaEventDisableTiming);
    cudaEventCreateWithFlags(&evJoin, cudaEventDisableTiming);

    cudaEventRecord(evFork, 0);              // main (capture) stream
    cudaStreamWaitEvent(side, evFork, 0);

    // Side branch: CSR build (launches 0,1,2 then 4,5,6 in submission order)
    zero_count_kernel<<<ceil_div(N, 256), 256, 0, side>>>(count, N);        // 0
    count_kernel<<<ceil_div(Etot, 256), 256, 0, side>>>(ei, E, Etot, count);// 1
    scan_block_kernel<<<nb, SCAN_BS, 0, side>>>(count, excl, bsum, N);      // 2

    // Main branch: layer-1 GEMM (submission index 3 -> profiler window)
    mma_gemm_kernel<128><<<dim3(2, ceil_div(N, 128)), 256, smem128>>>(      // 3
        x, W1, xpb, N, 256, 128, as1, ad1, s, d, 4);

    scan_sums_kernel<<<1, 256, 0, side>>>(bsum, nb);                        // 4
    scan_finish_kernel<<<ceil_div(N, 256), 256, 0, side>>>(excl, bsum, ptr, cursor,
                                                           N, Etot);        // 5
    scatter_kernel<<<ceil_div(Etot, 256), 256, 0, side>>>(ei, E, Etot, cursor, csr); // 6

    // Join: main waits for CSR completion
    cudaEventRecord(evJoin, side);
    cudaStreamWaitEvent(0, evJoin, 0);

    // --- Layer 1 gather ---
    gat_h4_kernel<<<ceil_div(N * 32, 256), 256>>>(ptr, csr, s, d, xpb, b1, bufB, N);

    // --- Layer 2: 256 -> (4,64) ---
    mma_gemm_kernel<128><<<dim3(2, ceil_div(N, 128)), 256, smem128>>>(
        bufB, W2, xpb, N, 256, 256, as2, ad2, s, d, 4);
    gat_h4_kernel<<<ceil_div(N * 32, 256), 256>>>(ptr, csr, s, d, xpb, b2, bufB, N);

    // --- Layer 3: 256 -> (1,64) + FC fused ---
    mma_gemm_kernel<64><<<dim3(1, ceil_div(N, 128)), 256, smem64>>>(
        bufB, W3, xpb, N, 64, 256, as3, ad3, s, d, 1);
    gat_h1_fc_kernel<<<ceil_div(N * 32, 256), 256>>>(ptr, csr, s, d, xpb, b3,
                                                     Wfc, bfc, out, N);
}